// round 14
// baseline (speedup 1.0000x reference)
#include <cuda_runtime.h>

#define H       20
#define SEQ     512
#define NB      4096
#define BPB     6                 // batches per block (120 compute + 8 head lanes)
#define THREADS 128
#define GRID    ((NB + BPB - 1) / BPB)   // 683

typedef unsigned long long u64;

__device__ __forceinline__ u64 pack2(float a, float b) {
    u64 r; asm("mov.b64 %0, {%1,%2};" : "=l"(r) : "f"(a), "f"(b)); return r;
}
__device__ __forceinline__ void unpack2(u64 v, float& a, float& b) {
    asm("mov.b64 {%0,%1}, %2;" : "=f"(a), "=f"(b) : "l"(v));
}
// Blackwell packed fp32 math (f32x2, PTX-only)
__device__ __forceinline__ u64 fma2(u64 a, u64 b, u64 c) {
    u64 d; asm("fma.rn.f32x2 %0, %1, %2, %3;" : "=l"(d) : "l"(a), "l"(b), "l"(c)); return d;
}
__device__ __forceinline__ u64 add2(u64 a, u64 b) {
    u64 d; asm("add.rn.f32x2 %0, %1, %2;" : "=l"(d) : "l"(a), "l"(b)); return d;
}
// HW tanh (MUFU.TANH) — measured safe: rel_err 1.56e-6 over the 512-step recurrence
__device__ __forceinline__ float tanh_ap(float v) {
    float r; asm("tanh.approx.f32 %0, %1;" : "=f"(r) : "f"(v)); return r;
}
__device__ __forceinline__ float sigmoid_ap(float v) {
    return fmaf(0.5f, tanh_ap(0.5f * v), 0.5f);   // FMUL + MUFU + FFMA
}

__global__ __launch_bounds__(THREADS, 5) void lstm_fused(
    const float* __restrict__ x,     const float* __restrict__ W_ih,
    const float* __restrict__ W_hh,  const float* __restrict__ b_ih,
    const float* __restrict__ b_hh,  const float* __restrict__ W_lin,
    const float* __restrict__ b_lin, float* __restrict__ out)
{
    // double-buffered h, duplicated {h,h} so LDS.128 feeds fma2 directly
    __shared__ __align__(16) float2 hbuf[2][BPB][H];
    // double-buffered h*W_lin partials for head lanes (pad 24 -> 96B rows)
    __shared__ __align__(16) float  psum[2][BPB][24];
    __shared__ float xs[BPB * SEQ];   // staged x rows (12 KB)

    const int tid  = threadIdx.x;
    const int b    = tid / H;               // local batch  (compute lanes)
    const int j    = tid % H;               // hidden unit  (compute lanes)
    const bool comp = tid < BPB * H;        // 120 compute lanes
    const int  hs   = tid - BPB * H;        // head slot on spare lanes
    const bool hact = (hs >= 0) && (hs < BPB) && (blockIdx.x * BPB + hs < NB);

    // Stage x for all 6 batches (coalesced; clamp out-of-range batch).
    for (int i = tid; i < BPB * SEQ; i += THREADS) {
        int gbx = blockIdx.x * BPB + (i >> 9);
        if (gbx > NB - 1) gbx = NB - 1;
        xs[i] = x[(size_t)gbx * SEQ + (i & (SEQ - 1))];
    }

    // All recurrent weights in registers: lane j owns gate rows
    // j(i), H+j(f), 2H+j(g), 3H+j(o), packed (i,f) and (g,o) -> 80 regs.
    u64 wif[H], wgo[H];
    u64 bif = 0, bgo = 0, wxif = 0, wxgo = 0;
    float wl = 0.0f;
    if (comp) {
#pragma unroll
        for (int k = 0; k < H; ++k) {
            wif[k] = pack2(W_hh[j * H + k],           W_hh[(H + j) * H + k]);
            wgo[k] = pack2(W_hh[(2 * H + j) * H + k], W_hh[(3 * H + j) * H + k]);
        }
        bif  = pack2(b_ih[j] + b_hh[j],             b_ih[H + j] + b_hh[H + j]);
        bgo  = pack2(b_ih[2 * H + j] + b_hh[2 * H + j],
                     b_ih[3 * H + j] + b_hh[3 * H + j]);
        wxif = pack2(W_ih[j],         W_ih[H + j]);
        wxgo = pack2(W_ih[2 * H + j], W_ih[3 * H + j]);
        wl   = W_lin[j];
        hbuf[0][b][j] = make_float2(0.0f, 0.0f);
    }
    const float bl = b_lin[0];
    float* ohead = hact ? (out + (size_t)(blockIdx.x * BPB + hs) * SEQ) : out;
    const float* xrow = xs + ((comp ? b : 0) << 9);
    const int bloc = comp ? b : 0;
    const int hloc = hact ? hs : 0;

    __syncthreads();   // covers xs preload + h init

    float c = 0.0f;

#pragma unroll 2
    for (int t = 0; t < SEQ; ++t) {
        const int r = t & 1, w = r ^ 1;
        if (comp) {
            const longlong2* hp = (const longlong2*)&hbuf[r][bloc][0];
            float xt = xrow[t];
            u64 x2 = pack2(xt, xt);

            u64 aIF = bif, aGO = bgo;
#pragma unroll
            for (int q = 0; q < H / 2; ++q) {
                longlong2 hh = hp[q];     // {h2q,h2q},{h2q+1,h2q+1} broadcast
                aIF = fma2((u64)hh.x, wif[2 * q],     aIF);
                aIF = fma2((u64)hh.y, wif[2 * q + 1], aIF);
                aGO = fma2((u64)hh.x, wgo[2 * q],     aGO);
                aGO = fma2((u64)hh.y, wgo[2 * q + 1], aGO);
            }
            u64 gIF = fma2(x2, wxif, aIF);
            u64 gGO = fma2(x2, wxgo, aGO);

            float gi, gf, gg, go;
            unpack2(gIF, gi, gf);
            unpack2(gGO, gg, go);
            float iv = sigmoid_ap(gi);
            float fv = sigmoid_ap(gf);
            float gv = tanh_ap(gg);
            float ov = sigmoid_ap(go);
            c = fmaf(fv, c, iv * gv);
            float h = ov * tanh_ap(c);

            hbuf[w][bloc][j] = make_float2(h, h);
            psum[w][bloc][j] = h * wl;
        }
        __syncthreads();
        if (hact) {
            // 20 partials -> packed add2 tree (5 LDS.128 + 9 add2)
            const ulonglong2* pq = (const ulonglong2*)&psum[w][hloc][0];
            ulonglong2 p0 = pq[0], p1 = pq[1], p2 = pq[2], p3 = pq[3], p4 = pq[4];
            u64 s0 = add2((u64)p0.x, (u64)p0.y);
            u64 s1 = add2((u64)p1.x, (u64)p1.y);
            u64 s2 = add2((u64)p2.x, (u64)p2.y);
            u64 s3 = add2((u64)p3.x, (u64)p3.y);
            u64 s4 = add2((u64)p4.x, (u64)p4.y);
            u64 s = add2(add2(add2(s0, s1), add2(s2, s3)), s4);
            float lo, hi;
            unpack2(s, lo, hi);
            ohead[t] = lo + hi + bl;
        }
    }
}

extern "C" void kernel_launch(void* const* d_in, const int* in_sizes, int n_in,
                              void* d_out, int out_size) {
    const float* x     = (const float*)d_in[0];
    const float* W_ih  = (const float*)d_in[1];
    const float* W_hh  = (const float*)d_in[2];
    const float* b_ih  = (const float*)d_in[3];
    const float* b_hh  = (const float*)d_in[4];
    const float* W_lin = (const float*)d_in[5];
    const float* b_lin = (const float*)d_in[6];
    float* out = (float*)d_out;

    lstm_fused<<<GRID, THREADS>>>(x, W_ih, W_hh, b_ih, b_hh, W_lin, b_lin, out);
}